// round 2
// baseline (speedup 1.0000x reference)
#include <cuda_runtime.h>
#include <math.h>

// ----------------------------------------------------------------------------
// Fused MLP3D kernel (fp32, SMEM-tiled, packed fma.rn.f32x2 mainloop).
// One block = 64 points, 256 threads.
// Activations in SMEM transposed: buf[k][pt], row stride LDB=68 floats.
// Weights staged in SMEM lane-DUPLICATED: (w_j, w_j, w_{j+1}, w_{j+1}) so a
// single LDS.128 feeds two packed-point FFMA2 operands.
//
// Pipeline per block:
//   embed (63 feats, zero-padded to 64)            -> bufB
//   GEMM0: x  = emb @ W0 + b0          (K=64/63)   -> bufA
//   GEMM1: h  = relu(x @ W1 + b1)      (K=256)     -> bufB
//   parts: relu(x[:,p] @ W1[p,p] + b1[p]) . Wc[p] + bc[p]   (uses bufA)
//   GEMM2: h2 = relu(h @ W2 + b2)      (K=256)     -> bufA
//   occ:   h2 @ Wocc + bocc
//
// Output: d_out[0..n) = occ ; d_out[n..5n) = part_class [N,4] row-major.
// ----------------------------------------------------------------------------

#define THREADS 256
#define TP      64
#define LDB     68
#define KC      32

typedef unsigned long long ull;

// shared-memory float offsets
#define OFF_A   0
#define OFF_B   (256 * LDB)               // 17408
#define OFF_W   (2 * 256 * LDB)           // 34816 (Wt2: KC*512 = 16384 floats)
#define OFF_RED (OFF_W + KC * 512)        // 51200
#define OFF_WC  (OFF_RED + 256)           // 51456
#define SMEM_FLOATS (OFF_WC + 64)         // 51520 floats = 206080 bytes

__device__ __forceinline__ ull fma2(ull a, ull b, ull c) {
    ull d;
    asm("fma.rn.f32x2 %0, %1, %2, %3;" : "=l"(d) : "l"(a), "l"(b), "l"(c));
    return d;
}

// out[i][j] = act(bias[j] + sum_k inT[k][i] * Wg[k][j]); result stored
// transposed to outT[j][i]. Wg row-major [Kact][256]; K padded loop bound,
// inT rows in [Kact, K) must be zero.
__device__ __forceinline__ void gemm_tile(
    const float* __restrict__ Wg, const float* __restrict__ bias,
    const float* inT, float* outT, float* Wt2,
    int K, int Kact, bool doRelu)
{
    const int t    = threadIdx.x;
    const int lane = t & 31;        // neuron base j = 2*lane + 64*rr + d
    const int i0   = (t >> 5) * 8;  // point group (warp-uniform)

    ull acc[4][2][4];               // [rr][d][point-pair], each = 2 fp32
#pragma unroll
    for (int rr = 0; rr < 4; ++rr)
#pragma unroll
        for (int d = 0; d < 2; ++d)
#pragma unroll
            for (int pp = 0; pp < 4; ++pp) acc[rr][d][pp] = 0ULL;

    for (int k0 = 0; k0 < K; k0 += KC) {
        __syncthreads();
        // stage Wt2[KC][512] duplicated: Wt2[row][2j]=Wt2[row][2j+1]=W[k0+row][j]
#pragma unroll
        for (int r = 0; r < 8; ++r) {
            int idx4 = t + r * 256;            // 0..2047
            int row  = idx4 >> 6;              // 32 rows, 64 float4-src per row
            int col  = (idx4 & 63) << 2;       // source col (j)
            float4 v = make_float4(0.f, 0.f, 0.f, 0.f);
            int gk = k0 + row;
            if (gk < Kact) v = *(const float4*)(Wg + gk * 256 + col);
            float* dst = Wt2 + row * 512 + 2 * col;
            *(float4*)(dst)     = make_float4(v.x, v.x, v.y, v.y);
            *(float4*)(dst + 4) = make_float4(v.z, v.z, v.w, v.w);
        }
        __syncthreads();

#pragma unroll 4
        for (int kk = 0; kk < KC; ++kk) {
            const float* xr = inT + (k0 + kk) * LDB + i0;  // warp-broadcast
            ulonglong2 xa = *(const ulonglong2*)xr;        // pairs (i0,i0+1),(i0+2,i0+3)
            ulonglong2 xb = *(const ulonglong2*)(xr + 4);
            ull xp[4] = {xa.x, xa.y, xb.x, xb.y};
            const float* wrow = Wt2 + kk * 512 + 4 * lane;
#pragma unroll
            for (int rr = 0; rr < 4; ++rr) {
                ulonglong2 wv = *(const ulonglong2*)(wrow + 128 * rr);
#pragma unroll
                for (int pp = 0; pp < 4; ++pp) {
                    acc[rr][0][pp] = fma2(wv.x, xp[pp], acc[rr][0][pp]);
                    acc[rr][1][pp] = fma2(wv.y, xp[pp], acc[rr][1][pp]);
                }
            }
        }
    }

    // bias + activation + transposed store
#pragma unroll
    for (int rr = 0; rr < 4; ++rr)
#pragma unroll
        for (int d = 0; d < 2; ++d) {
            int j = 2 * lane + 64 * rr + d;
            float b = bias[j];
#pragma unroll
            for (int pp = 0; pp < 4; ++pp) {
                float2 v = *(float2*)&acc[rr][d][pp];
                float v0 = v.x + b, v1 = v.y + b;
                if (doRelu) { v0 = fmaxf(v0, 0.f); v1 = fmaxf(v1, 0.f); }
                outT[j * LDB + i0 + 2 * pp]     = v0;
                outT[j * LDB + i0 + 2 * pp + 1] = v1;
            }
        }
    __syncthreads();
}

extern "C" __global__ void __launch_bounds__(THREADS, 1)
mlp3d_kernel(const float* __restrict__ coords,
             const float* __restrict__ W0, const float* __restrict__ b0,
             const float* __restrict__ W1, const float* __restrict__ b1,
             const float* __restrict__ W2, const float* __restrict__ b2,
             const float* __restrict__ Wocc, const float* __restrict__ bocc,
             const float* __restrict__ Wc, const float* __restrict__ bc,
             float* __restrict__ out, int n)
{
    extern __shared__ float sm[];
    float* bufA = sm + OFF_A;
    float* bufB = sm + OFF_B;
    float* Wt   = sm + OFF_W;     // also reused (scalar layout) by parts/occ
    float* sRed = sm + OFF_RED;
    float* sWc  = sm + OFF_WC;

    const int t   = threadIdx.x;
    const int pt0 = blockIdx.x * TP;

    // ---- embedding -> bufB rows 0..62, row 63 zeroed ----
    if (t < TP) bufB[63 * LDB + t] = 0.f;
    if (t < TP * 3) {
        int pt = t / 3, d = t % 3;
        float c = 0.f;
        if (pt0 + pt < n) c = coords[(pt0 + pt) * 3 + d];
        bufB[d * LDB + pt] = c;
        float ang = c;
#pragma unroll
        for (int f = 0; f < 10; ++f) {
            float s, co;
            sincosf(ang, &s, &co);
            bufB[(3 + 6 * f + d) * LDB + pt]     = s;
            bufB[(3 + 6 * f + 3 + d) * LDB + pt] = co;
            ang += ang;
        }
    }
    __syncthreads();

    gemm_tile(W0, b0, bufB, bufA, Wt, 64, 63, false);    // x  -> bufA
    gemm_tile(W1, b1, bufA, bufB, Wt, 256, 256, true);   // h  -> bufB

    // ---- part branches (need x in bufA) ----
    {
        const int pt = t & 63;
        const int q  = t >> 6;          // warp-uniform j-quarter
        for (int p = 0; p < 4; ++p) {
            const int P = p * 64;
            // stage W1[P:P+64, P:P+64] into Wt (row stride 64 floats)
#pragma unroll
            for (int r = 0; r < 4; ++r) {
                int idx4 = t + r * 256;          // 0..1023
                int row  = idx4 >> 4;            // 16 float4 per row
                int col  = (idx4 & 15) << 2;
                *(float4*)(Wt + row * 64 + col) =
                    *(const float4*)(W1 + (P + row) * 256 + P + col);
            }
            if (t < 64) sWc[t] = Wc[p * 256 + P + t];
            __syncthreads();

            float acc[16];
#pragma unroll
            for (int jj = 0; jj < 16; ++jj) acc[jj] = b1[P + q * 16 + jj];
#pragma unroll
            for (int kc = 0; kc < 4; ++kc) {
                float xk[16];
#pragma unroll
                for (int k = 0; k < 16; ++k)
                    xk[k] = bufA[(P + kc * 16 + k) * LDB + pt];
#pragma unroll
                for (int jj = 0; jj < 16; ++jj)
#pragma unroll
                    for (int k = 0; k < 16; ++k)
                        acc[jj] = fmaf(xk[k],
                                       Wt[(kc * 16 + k) * 64 + q * 16 + jj],
                                       acc[jj]);
            }
            float s = 0.f;
#pragma unroll
            for (int jj = 0; jj < 16; ++jj)
                s = fmaf(fmaxf(acc[jj], 0.f), sWc[q * 16 + jj], s);
            sRed[q * 64 + pt] = s;
            __syncthreads();
            if (t < 64 && pt0 + t < n) {
                float cls = bc[p] + sRed[t] + sRed[64 + t]
                                  + sRed[128 + t] + sRed[192 + t];
                out[n + (pt0 + t) * 4 + p] = cls;
            }
            __syncthreads();
        }
    }

    gemm_tile(W2, b2, bufB, bufA, Wt, 256, 256, true);   // h2 -> bufA

    // ---- occ head ----
    Wt[t] = Wocc[t];
    __syncthreads();
    {
        const int pt = t & 63;
        const int q  = t >> 6;
        float s = 0.f;
#pragma unroll
        for (int j = 0; j < 64; ++j)
            s = fmaf(bufA[(q * 64 + j) * LDB + pt], Wt[q * 64 + j], s);
        sRed[q * 64 + pt] = s;
        __syncthreads();
        if (t < 64 && pt0 + t < n)
            out[pt0 + t] = bocc[0] + sRed[t] + sRed[64 + t]
                                   + sRed[128 + t] + sRed[192 + t];
    }
}

extern "C" void kernel_launch(void* const* d_in, const int* in_sizes, int n_in,
                              void* d_out, int out_size)
{
    const float* coords = (const float*)d_in[0];
    const float* W0   = (const float*)d_in[1];
    const float* b0   = (const float*)d_in[2];
    const float* W1   = (const float*)d_in[3];
    const float* b1   = (const float*)d_in[4];
    const float* W2   = (const float*)d_in[5];
    const float* b2   = (const float*)d_in[6];
    const float* Wocc = (const float*)d_in[7];
    const float* bocc = (const float*)d_in[8];
    const float* Wc   = (const float*)d_in[9];
    const float* bc   = (const float*)d_in[10];
    float* out = (float*)d_out;

    int n = in_sizes[0] / 3;
    int blocks = (n + TP - 1) / TP;
    size_t smem = SMEM_FLOATS * sizeof(float);
    cudaFuncSetAttribute(mlp3d_kernel,
                         cudaFuncAttributeMaxDynamicSharedMemorySize,
                         (int)smem);
    mlp3d_kernel<<<blocks, THREADS, smem>>>(coords, W0, b0, W1, b1, W2, b2,
                                            Wocc, bocc, Wc, bc, out, n);
}